// round 11
// baseline (speedup 1.0000x reference)
#include <cuda_runtime.h>

// GRU: B=16384, T=1024, H=256. Inputs (metadata order):
// 0:x(B,T) 1:w_ih(768,1) 2:w_hh(768,256) 3:b_ih(768) 4:b_hh(768) 5:w_out(1,256) 6:b_out(1)
// Output: (B,T) fp32.
//
// R9: 2 CTAs/SM (MT=16), single __syncthreads per step via double-buffered h /
// part / prefetched x tiles, h stored as float4-of-4-rows for LDS.128 broadcast.

#define MT 16          // batch rows per CTA
#define PAIRS 8        // MT/2 f32x2 row-pairs per thread
#define PG 4           // pair-groups (4 rows each)

// Transposed weights: wT[i*768 + gate*256 + j] = w_hh[(gate*256+j)*256 + i]
__device__ float g_wT[256 * 768];

__device__ __forceinline__ unsigned long long pack2(float w) {
    unsigned long long r;
    unsigned u = __float_as_uint(w);
    asm("mov.b64 %0, {%1, %1};" : "=l"(r) : "r"(u));
    return r;
}

// Blackwell packed fp32 FMA (FFMA2 in SASS): acc += a * b (2 lanes).
__device__ __forceinline__ void fma2(unsigned long long& acc,
                                     unsigned long long a,
                                     unsigned long long b) {
    asm("fma.rn.f32x2 %0, %1, %2, %0;" : "+l"(acc) : "l"(a), "l"(b));
}

__device__ __forceinline__ float sigm(float v) {
    return __fdividef(1.f, 1.f + __expf(-v));
}
__device__ __forceinline__ float tanh_fast(float v) {
    float u = __expf(-2.f * fabsf(v));          // in (0,1] -> no overflow/NaN
    float t = (1.f - u) * __fdividef(1.f, 1.f + u);
    return copysignf(t, v);
}

__global__ void k_transpose(const float* __restrict__ w_hh) {
    int idx = blockIdx.x * 256 + threadIdx.x;   // idx = j*256 + i
    if (idx < 768 * 256) {
        g_wT[(idx & 255) * 768 + (idx >> 8)] = w_hh[idx];
    }
}

__global__ __launch_bounds__(256, 2) void k_gru(
    const float* __restrict__ x,
    const float* __restrict__ w_ih,
    const float* __restrict__ b_ih,
    const float* __restrict__ b_hh,
    const float* __restrict__ w_out,
    const float* __restrict__ b_out,
    float* __restrict__ out)
{
    // h double-buffer: hq[buf][pg][i] = float4(h[4pg..4pg+3][i]).
    // GEMM reads buf (t&1) via broadcast LDS.128; epilogue writes buf^1 via STS.128.
    __shared__ float4 hq[2][PG][256];
    __shared__ float  xs[2][MT][32];     // x tiles, prefetched 32 steps ahead
    __shared__ float2 part[2][8][PAIRS]; // per-warp output partials, double-buffered

    const int tid  = threadIdx.x;
    const int lane = tid & 31;
    const int wid  = tid >> 5;
    const int b0   = blockIdx.x * MT;

    // Init: zero h buf0, preload x tile 0. Covered by the t=0 loop-top sync.
    #pragma unroll
    for (int pg = 0; pg < PG; pg++)
        hq[0][pg][tid] = make_float4(0.f, 0.f, 0.f, 0.f);
    if (tid < 128) {
        int m = tid >> 3, q = tid & 7;
        float4 v = *reinterpret_cast<const float4*>(x + (b0 + m) * 1024 + 4 * q);
        *reinterpret_cast<float4*>(&xs[0][m][4 * q]) = v;
    }

    // Per-thread (column j = tid) constants.
    const float wiR = w_ih[tid], wiZ = w_ih[256 + tid], wiN = w_ih[512 + tid];
    const float bR  = b_ih[tid]       + b_hh[tid];
    const float bZ  = b_ih[256 + tid] + b_hh[256 + tid];
    const float biN = b_ih[512 + tid];
    const float bhN = b_hh[512 + tid];
    const float wo  = w_out[tid];
    const float bo  = b_out[0];
    const float* wp = g_wT + tid;

    for (int t = 0; t < 1024; t++) {
        const int hb = t & 1;
        const int xb = (t >> 5) & 1;

        __syncthreads();  // the ONE barrier per step

        // Emit out[t-1] from partials written at end of step t-1.
        if (tid < MT && t > 0) {
            int p = tid >> 1;
            float s = bo;
            #pragma unroll
            for (int w = 0; w < 8; w++) {
                float2 v = part[(t + 1) & 1][w][p];
                s += (tid & 1) ? v.y : v.x;
            }
            out[(b0 + tid) * 1024 + (t - 1)] = s;
        }

        // Prefetch next 32-step x tile (consumed from step t+32 onward).
        if ((t & 31) == 0 && t + 32 < 1024 && tid < 128) {
            int m = tid >> 3, q = tid & 7;
            float4 v = *reinterpret_cast<const float4*>(
                x + (b0 + m) * 1024 + (t + 32) + 4 * q);
            *reinterpret_cast<float4*>(&xs[xb ^ 1][m][4 * q]) = v;
        }

        // ---- GEMM: gh[m, gate*256+tid] = sum_i h[m,i] * w_hh[gate*256+tid, i] ----
        const float4* hbase = &hq[hb][0][0];
        unsigned long long aR[PAIRS], aZ[PAIRS], aN[PAIRS];
        #pragma unroll
        for (int p = 0; p < PAIRS; p++) { aR[p] = 0ull; aZ[p] = 0ull; aN[p] = 0ull; }

        for (int i0 = 0; i0 < 256; i0 += 8) {
            float wr[8], wz[8], wn[8];
            #pragma unroll
            for (int u = 0; u < 8; u++) {   // 24 front-batched coalesced LDGs (MLP)
                const float* bp = wp + (i0 + u) * 768;
                wr[u] = bp[0]; wz[u] = bp[256]; wn[u] = bp[512];
            }
            #pragma unroll
            for (int u = 0; u < 8; u++) {
                unsigned long long br = pack2(wr[u]);
                unsigned long long bz = pack2(wz[u]);
                unsigned long long bn = pack2(wn[u]);
                #pragma unroll
                for (int pg = 0; pg < PG; pg++) {
                    // broadcast LDS.128: 4 rows of h at column i0+u
                    ulonglong2 hv = *reinterpret_cast<const ulonglong2*>(
                        &hbase[pg * 256 + (i0 + u)]);
                    fma2(aR[2 * pg],     hv.x, br);
                    fma2(aR[2 * pg + 1], hv.y, br);
                    fma2(aZ[2 * pg],     hv.x, bz);
                    fma2(aZ[2 * pg + 1], hv.y, bz);
                    fma2(aN[2 * pg],     hv.x, bn);
                    fma2(aN[2 * pg + 1], hv.y, bn);
                }
            }
        }

        // ---- Gates + h update + output contribution ----
        const int tt = t & 31;
        float4* nbase = &hq[hb ^ 1][0][0];
        float2 ov[PAIRS];
        #pragma unroll
        for (int pg = 0; pg < PG; pg++) {
            float4 ho = hbase[pg * 256 + tid];   // old h rows 4pg..4pg+3, col tid
            float hn[4];
            #pragma unroll
            for (int half = 0; half < 2; half++) {
                int p = 2 * pg + half;
                float2 ar = *reinterpret_cast<float2*>(&aR[p]);
                float2 az = *reinterpret_cast<float2*>(&aZ[p]);
                float2 an = *reinterpret_cast<float2*>(&aN[p]);
                float x0 = xs[xb][2 * p][tt], x1 = xs[xb][2 * p + 1][tt];
                float h0o = half ? ho.z : ho.x;
                float h1o = half ? ho.w : ho.y;

                float r0 = sigm(fmaf(x0, wiR, bR) + ar.x);
                float r1 = sigm(fmaf(x1, wiR, bR) + ar.y);
                float z0 = sigm(fmaf(x0, wiZ, bZ) + az.x);
                float z1 = sigm(fmaf(x1, wiZ, bZ) + az.y);
                float n0 = tanh_fast(fmaf(x0, wiN, biN) + r0 * (an.x + bhN));
                float n1 = tanh_fast(fmaf(x1, wiN, biN) + r1 * (an.y + bhN));
                float h0 = n0 + z0 * (h0o - n0);   // (1-z)*n + z*h
                float h1 = n1 + z1 * (h1o - n1);

                hn[2 * half] = h0; hn[2 * half + 1] = h1;
                ov[p] = make_float2(fmaxf(h0, 0.f) * wo, fmaxf(h1, 0.f) * wo);
            }
            nbase[pg * 256 + tid] = make_float4(hn[0], hn[1], hn[2], hn[3]);
        }

        // ---- Output partials: warp butterfly over columns ----
        #pragma unroll
        for (int p = 0; p < PAIRS; p++) {
            float ox = ov[p].x, oy = ov[p].y;
            #pragma unroll
            for (int off = 16; off; off >>= 1) {
                ox += __shfl_xor_sync(0xffffffffu, ox, off);
                oy += __shfl_xor_sync(0xffffffffu, oy, off);
            }
            if (lane == 0) part[hb][wid][p] = make_float2(ox, oy);
        }
        // no trailing sync: next step's top sync publishes hq[hb^1] and part[hb]
    }

    // Flush out[1023].
    __syncthreads();
    if (tid < MT) {
        int p = tid >> 1;
        float s = bo;
        #pragma unroll
        for (int w = 0; w < 8; w++) {
            float2 v = part[1][w][p];   // 1023 & 1
            s += (tid & 1) ? v.y : v.x;
        }
        out[(b0 + tid) * 1024 + 1023] = s;
    }
}

extern "C" void kernel_launch(void* const* d_in, const int* in_sizes, int n_in,
                              void* d_out, int out_size) {
    const float* x     = (const float*)d_in[0];
    const float* w_ih  = (const float*)d_in[1];
    const float* w_hh  = (const float*)d_in[2];
    const float* b_ih  = (const float*)d_in[3];
    const float* b_hh  = (const float*)d_in[4];
    const float* w_out = (const float*)d_in[5];
    const float* b_out = (const float*)d_in[6];
    float* out = (float*)d_out;

    k_transpose<<<768, 256>>>(w_hh);
    k_gru<<<1024, 256>>>(x, w_ih, b_ih, b_hh, w_out, b_out, out);
}

// round 12
// speedup vs baseline: 1.0007x; 1.0007x over previous
#include <cuda_runtime.h>

// GRU: B=16384, T=1024, H=256. Inputs (metadata order):
// 0:x(B,T) 1:w_ih(768,1) 2:w_hh(768,256) 3:b_ih(768) 4:b_hh(768) 5:w_out(1,256) 6:b_out(1)
// Output: (B,T) fp32.
//
// R9: 2 CTAs/SM (MT=16), single __syncthreads per step via double-buffered h /
// part / prefetched x tiles, h stored as float4-of-4-rows for LDS.128 broadcast.

#define MT 16          // batch rows per CTA
#define PAIRS 8        // MT/2 f32x2 row-pairs per thread
#define PG 4           // pair-groups (4 rows each)

// Transposed weights: wT[i*768 + gate*256 + j] = w_hh[(gate*256+j)*256 + i]
__device__ float g_wT[256 * 768];

__device__ __forceinline__ unsigned long long pack2(float w) {
    unsigned long long r;
    unsigned u = __float_as_uint(w);
    asm("mov.b64 %0, {%1, %1};" : "=l"(r) : "r"(u));
    return r;
}

// Blackwell packed fp32 FMA (FFMA2 in SASS): acc += a * b (2 lanes).
__device__ __forceinline__ void fma2(unsigned long long& acc,
                                     unsigned long long a,
                                     unsigned long long b) {
    asm("fma.rn.f32x2 %0, %1, %2, %0;" : "+l"(acc) : "l"(a), "l"(b));
}

__device__ __forceinline__ float sigm(float v) {
    return __fdividef(1.f, 1.f + __expf(-v));
}
__device__ __forceinline__ float tanh_fast(float v) {
    float u = __expf(-2.f * fabsf(v));          // in (0,1] -> no overflow/NaN
    float t = (1.f - u) * __fdividef(1.f, 1.f + u);
    return copysignf(t, v);
}

__global__ void k_transpose(const float* __restrict__ w_hh) {
    int idx = blockIdx.x * 256 + threadIdx.x;   // idx = j*256 + i
    if (idx < 768 * 256) {
        g_wT[(idx & 255) * 768 + (idx >> 8)] = w_hh[idx];
    }
}

__global__ __launch_bounds__(256, 2) void k_gru(
    const float* __restrict__ x,
    const float* __restrict__ w_ih,
    const float* __restrict__ b_ih,
    const float* __restrict__ b_hh,
    const float* __restrict__ w_out,
    const float* __restrict__ b_out,
    float* __restrict__ out)
{
    // h double-buffer: hq[buf][pg][i] = float4(h[4pg..4pg+3][i]).
    // GEMM reads buf (t&1) via broadcast LDS.128; epilogue writes buf^1 via STS.128.
    __shared__ float4 hq[2][PG][256];
    __shared__ float  xs[2][MT][32];     // x tiles, prefetched 32 steps ahead
    __shared__ float2 part[2][8][PAIRS]; // per-warp output partials, double-buffered

    const int tid  = threadIdx.x;
    const int lane = tid & 31;
    const int wid  = tid >> 5;
    const int b0   = blockIdx.x * MT;

    // Init: zero h buf0, preload x tile 0. Covered by the t=0 loop-top sync.
    #pragma unroll
    for (int pg = 0; pg < PG; pg++)
        hq[0][pg][tid] = make_float4(0.f, 0.f, 0.f, 0.f);
    if (tid < 128) {
        int m = tid >> 3, q = tid & 7;
        float4 v = *reinterpret_cast<const float4*>(x + (b0 + m) * 1024 + 4 * q);
        *reinterpret_cast<float4*>(&xs[0][m][4 * q]) = v;
    }

    // Per-thread (column j = tid) constants.
    const float wiR = w_ih[tid], wiZ = w_ih[256 + tid], wiN = w_ih[512 + tid];
    const float bR  = b_ih[tid]       + b_hh[tid];
    const float bZ  = b_ih[256 + tid] + b_hh[256 + tid];
    const float biN = b_ih[512 + tid];
    const float bhN = b_hh[512 + tid];
    const float wo  = w_out[tid];
    const float bo  = b_out[0];
    const float* wp = g_wT + tid;

    for (int t = 0; t < 1024; t++) {
        const int hb = t & 1;
        const int xb = (t >> 5) & 1;

        __syncthreads();  // the ONE barrier per step

        // Emit out[t-1] from partials written at end of step t-1.
        if (tid < MT && t > 0) {
            int p = tid >> 1;
            float s = bo;
            #pragma unroll
            for (int w = 0; w < 8; w++) {
                float2 v = part[(t + 1) & 1][w][p];
                s += (tid & 1) ? v.y : v.x;
            }
            out[(b0 + tid) * 1024 + (t - 1)] = s;
        }

        // Prefetch next 32-step x tile (consumed from step t+32 onward).
        if ((t & 31) == 0 && t + 32 < 1024 && tid < 128) {
            int m = tid >> 3, q = tid & 7;
            float4 v = *reinterpret_cast<const float4*>(
                x + (b0 + m) * 1024 + (t + 32) + 4 * q);
            *reinterpret_cast<float4*>(&xs[xb ^ 1][m][4 * q]) = v;
        }

        // ---- GEMM: gh[m, gate*256+tid] = sum_i h[m,i] * w_hh[gate*256+tid, i] ----
        const float4* hbase = &hq[hb][0][0];
        unsigned long long aR[PAIRS], aZ[PAIRS], aN[PAIRS];
        #pragma unroll
        for (int p = 0; p < PAIRS; p++) { aR[p] = 0ull; aZ[p] = 0ull; aN[p] = 0ull; }

        for (int i0 = 0; i0 < 256; i0 += 8) {
            float wr[8], wz[8], wn[8];
            #pragma unroll
            for (int u = 0; u < 8; u++) {   // 24 front-batched coalesced LDGs (MLP)
                const float* bp = wp + (i0 + u) * 768;
                wr[u] = bp[0]; wz[u] = bp[256]; wn[u] = bp[512];
            }
            #pragma unroll
            for (int u = 0; u < 8; u++) {
                unsigned long long br = pack2(wr[u]);
                unsigned long long bz = pack2(wz[u]);
                unsigned long long bn = pack2(wn[u]);
                #pragma unroll
                for (int pg = 0; pg < PG; pg++) {
                    // broadcast LDS.128: 4 rows of h at column i0+u
                    ulonglong2 hv = *reinterpret_cast<const ulonglong2*>(
                        &hbase[pg * 256 + (i0 + u)]);
                    fma2(aR[2 * pg],     hv.x, br);
                    fma2(aR[2 * pg + 1], hv.y, br);
                    fma2(aZ[2 * pg],     hv.x, bz);
                    fma2(aZ[2 * pg + 1], hv.y, bz);
                    fma2(aN[2 * pg],     hv.x, bn);
                    fma2(aN[2 * pg + 1], hv.y, bn);
                }
            }
        }

        // ---- Gates + h update + output contribution ----
        const int tt = t & 31;
        float4* nbase = &hq[hb ^ 1][0][0];
        float2 ov[PAIRS];
        #pragma unroll
        for (int pg = 0; pg < PG; pg++) {
            float4 ho = hbase[pg * 256 + tid];   // old h rows 4pg..4pg+3, col tid
            float hn[4];
            #pragma unroll
            for (int half = 0; half < 2; half++) {
                int p = 2 * pg + half;
                float2 ar = *reinterpret_cast<float2*>(&aR[p]);
                float2 az = *reinterpret_cast<float2*>(&aZ[p]);
                float2 an = *reinterpret_cast<float2*>(&aN[p]);
                float x0 = xs[xb][2 * p][tt], x1 = xs[xb][2 * p + 1][tt];
                float h0o = half ? ho.z : ho.x;
                float h1o = half ? ho.w : ho.y;

                float r0 = sigm(fmaf(x0, wiR, bR) + ar.x);
                float r1 = sigm(fmaf(x1, wiR, bR) + ar.y);
                float z0 = sigm(fmaf(x0, wiZ, bZ) + az.x);
                float z1 = sigm(fmaf(x1, wiZ, bZ) + az.y);
                float n0 = tanh_fast(fmaf(x0, wiN, biN) + r0 * (an.x + bhN));
                float n1 = tanh_fast(fmaf(x1, wiN, biN) + r1 * (an.y + bhN));
                float h0 = n0 + z0 * (h0o - n0);   // (1-z)*n + z*h
                float h1 = n1 + z1 * (h1o - n1);

                hn[2 * half] = h0; hn[2 * half + 1] = h1;
                ov[p] = make_float2(fmaxf(h0, 0.f) * wo, fmaxf(h1, 0.f) * wo);
            }
            nbase[pg * 256 + tid] = make_float4(hn[0], hn[1], hn[2], hn[3]);
        }

        // ---- Output partials: warp butterfly over columns ----
        #pragma unroll
        for (int p = 0; p < PAIRS; p++) {
            float ox = ov[p].x, oy = ov[p].y;
            #pragma unroll
            for (int off = 16; off; off >>= 1) {
                ox += __shfl_xor_sync(0xffffffffu, ox, off);
                oy += __shfl_xor_sync(0xffffffffu, oy, off);
            }
            if (lane == 0) part[hb][wid][p] = make_float2(ox, oy);
        }
        // no trailing sync: next step's top sync publishes hq[hb^1] and part[hb]
    }

    // Flush out[1023].
    __syncthreads();
    if (tid < MT) {
        int p = tid >> 1;
        float s = bo;
        #pragma unroll
        for (int w = 0; w < 8; w++) {
            float2 v = part[1][w][p];   // 1023 & 1
            s += (tid & 1) ? v.y : v.x;
        }
        out[(b0 + tid) * 1024 + 1023] = s;
    }
}

extern "C" void kernel_launch(void* const* d_in, const int* in_sizes, int n_in,
                              void* d_out, int out_size) {
    const float* x     = (const float*)d_in[0];
    const float* w_ih  = (const float*)d_in[1];
    const float* w_hh  = (const float*)d_in[2];
    const float* b_ih  = (const float*)d_in[3];
    const float* b_hh  = (const float*)d_in[4];
    const float* w_out = (const float*)d_in[5];
    const float* b_out = (const float*)d_in[6];
    float* out = (float*)d_out;

    k_transpose<<<768, 256>>>(w_hh);
    k_gru<<<1024, 256>>>(x, w_ih, b_ih, b_hh, w_out, b_out, out);
}

// round 14
// speedup vs baseline: 1.0015x; 1.0008x over previous
#include <cuda_runtime.h>

// GRU: B=16384, T=1024, H=256. Inputs (metadata order):
// 0:x(B,T) 1:w_ih(768,1) 2:w_hh(768,256) 3:b_ih(768) 4:b_hh(768) 5:w_out(1,256) 6:b_out(1)
// Output: (B,T) fp32.
//
// R9: 2 CTAs/SM (MT=16), single __syncthreads per step via double-buffered h /
// part / prefetched x tiles, h stored as float4-of-4-rows for LDS.128 broadcast.

#define MT 16          // batch rows per CTA
#define PAIRS 8        // MT/2 f32x2 row-pairs per thread
#define PG 4           // pair-groups (4 rows each)

// Transposed weights: wT[i*768 + gate*256 + j] = w_hh[(gate*256+j)*256 + i]
__device__ float g_wT[256 * 768];

__device__ __forceinline__ unsigned long long pack2(float w) {
    unsigned long long r;
    unsigned u = __float_as_uint(w);
    asm("mov.b64 %0, {%1, %1};" : "=l"(r) : "r"(u));
    return r;
}

// Blackwell packed fp32 FMA (FFMA2 in SASS): acc += a * b (2 lanes).
__device__ __forceinline__ void fma2(unsigned long long& acc,
                                     unsigned long long a,
                                     unsigned long long b) {
    asm("fma.rn.f32x2 %0, %1, %2, %0;" : "+l"(acc) : "l"(a), "l"(b));
}

__device__ __forceinline__ float sigm(float v) {
    return __fdividef(1.f, 1.f + __expf(-v));
}
__device__ __forceinline__ float tanh_fast(float v) {
    float u = __expf(-2.f * fabsf(v));          // in (0,1] -> no overflow/NaN
    float t = (1.f - u) * __fdividef(1.f, 1.f + u);
    return copysignf(t, v);
}

__global__ void k_transpose(const float* __restrict__ w_hh) {
    int idx = blockIdx.x * 256 + threadIdx.x;   // idx = j*256 + i
    if (idx < 768 * 256) {
        g_wT[(idx & 255) * 768 + (idx >> 8)] = w_hh[idx];
    }
}

__global__ __launch_bounds__(256, 2) void k_gru(
    const float* __restrict__ x,
    const float* __restrict__ w_ih,
    const float* __restrict__ b_ih,
    const float* __restrict__ b_hh,
    const float* __restrict__ w_out,
    const float* __restrict__ b_out,
    float* __restrict__ out)
{
    // h double-buffer: hq[buf][pg][i] = float4(h[4pg..4pg+3][i]).
    // GEMM reads buf (t&1) via broadcast LDS.128; epilogue writes buf^1 via STS.128.
    __shared__ float4 hq[2][PG][256];
    __shared__ float  xs[2][MT][32];     // x tiles, prefetched 32 steps ahead
    __shared__ float2 part[2][8][PAIRS]; // per-warp output partials, double-buffered

    const int tid  = threadIdx.x;
    const int lane = tid & 31;
    const int wid  = tid >> 5;
    const int b0   = blockIdx.x * MT;

    // Init: zero h buf0, preload x tile 0. Covered by the t=0 loop-top sync.
    #pragma unroll
    for (int pg = 0; pg < PG; pg++)
        hq[0][pg][tid] = make_float4(0.f, 0.f, 0.f, 0.f);
    if (tid < 128) {
        int m = tid >> 3, q = tid & 7;
        float4 v = *reinterpret_cast<const float4*>(x + (b0 + m) * 1024 + 4 * q);
        *reinterpret_cast<float4*>(&xs[0][m][4 * q]) = v;
    }

    // Per-thread (column j = tid) constants.
    const float wiR = w_ih[tid], wiZ = w_ih[256 + tid], wiN = w_ih[512 + tid];
    const float bR  = b_ih[tid]       + b_hh[tid];
    const float bZ  = b_ih[256 + tid] + b_hh[256 + tid];
    const float biN = b_ih[512 + tid];
    const float bhN = b_hh[512 + tid];
    const float wo  = w_out[tid];
    const float bo  = b_out[0];
    const float* wp = g_wT + tid;

    for (int t = 0; t < 1024; t++) {
        const int hb = t & 1;
        const int xb = (t >> 5) & 1;

        __syncthreads();  // the ONE barrier per step

        // Emit out[t-1] from partials written at end of step t-1.
        if (tid < MT && t > 0) {
            int p = tid >> 1;
            float s = bo;
            #pragma unroll
            for (int w = 0; w < 8; w++) {
                float2 v = part[(t + 1) & 1][w][p];
                s += (tid & 1) ? v.y : v.x;
            }
            out[(b0 + tid) * 1024 + (t - 1)] = s;
        }

        // Prefetch next 32-step x tile (consumed from step t+32 onward).
        if ((t & 31) == 0 && t + 32 < 1024 && tid < 128) {
            int m = tid >> 3, q = tid & 7;
            float4 v = *reinterpret_cast<const float4*>(
                x + (b0 + m) * 1024 + (t + 32) + 4 * q);
            *reinterpret_cast<float4*>(&xs[xb ^ 1][m][4 * q]) = v;
        }

        // ---- GEMM: gh[m, gate*256+tid] = sum_i h[m,i] * w_hh[gate*256+tid, i] ----
        const float4* hbase = &hq[hb][0][0];
        unsigned long long aR[PAIRS], aZ[PAIRS], aN[PAIRS];
        #pragma unroll
        for (int p = 0; p < PAIRS; p++) { aR[p] = 0ull; aZ[p] = 0ull; aN[p] = 0ull; }

        for (int i0 = 0; i0 < 256; i0 += 8) {
            float wr[8], wz[8], wn[8];
            #pragma unroll
            for (int u = 0; u < 8; u++) {   // 24 front-batched coalesced LDGs (MLP)
                const float* bp = wp + (i0 + u) * 768;
                wr[u] = bp[0]; wz[u] = bp[256]; wn[u] = bp[512];
            }
            #pragma unroll
            for (int u = 0; u < 8; u++) {
                unsigned long long br = pack2(wr[u]);
                unsigned long long bz = pack2(wz[u]);
                unsigned long long bn = pack2(wn[u]);
                #pragma unroll
                for (int pg = 0; pg < PG; pg++) {
                    // broadcast LDS.128: 4 rows of h at column i0+u
                    ulonglong2 hv = *reinterpret_cast<const ulonglong2*>(
                        &hbase[pg * 256 + (i0 + u)]);
                    fma2(aR[2 * pg],     hv.x, br);
                    fma2(aR[2 * pg + 1], hv.y, br);
                    fma2(aZ[2 * pg],     hv.x, bz);
                    fma2(aZ[2 * pg + 1], hv.y, bz);
                    fma2(aN[2 * pg],     hv.x, bn);
                    fma2(aN[2 * pg + 1], hv.y, bn);
                }
            }
        }

        // ---- Gates + h update + output contribution ----
        const int tt = t & 31;
        float4* nbase = &hq[hb ^ 1][0][0];
        float2 ov[PAIRS];
        #pragma unroll
        for (int pg = 0; pg < PG; pg++) {
            float4 ho = hbase[pg * 256 + tid];   // old h rows 4pg..4pg+3, col tid
            float hn[4];
            #pragma unroll
            for (int half = 0; half < 2; half++) {
                int p = 2 * pg + half;
                float2 ar = *reinterpret_cast<float2*>(&aR[p]);
                float2 az = *reinterpret_cast<float2*>(&aZ[p]);
                float2 an = *reinterpret_cast<float2*>(&aN[p]);
                float x0 = xs[xb][2 * p][tt], x1 = xs[xb][2 * p + 1][tt];
                float h0o = half ? ho.z : ho.x;
                float h1o = half ? ho.w : ho.y;

                float r0 = sigm(fmaf(x0, wiR, bR) + ar.x);
                float r1 = sigm(fmaf(x1, wiR, bR) + ar.y);
                float z0 = sigm(fmaf(x0, wiZ, bZ) + az.x);
                float z1 = sigm(fmaf(x1, wiZ, bZ) + az.y);
                float n0 = tanh_fast(fmaf(x0, wiN, biN) + r0 * (an.x + bhN));
                float n1 = tanh_fast(fmaf(x1, wiN, biN) + r1 * (an.y + bhN));
                float h0 = n0 + z0 * (h0o - n0);   // (1-z)*n + z*h
                float h1 = n1 + z1 * (h1o - n1);

                hn[2 * half] = h0; hn[2 * half + 1] = h1;
                ov[p] = make_float2(fmaxf(h0, 0.f) * wo, fmaxf(h1, 0.f) * wo);
            }
            nbase[pg * 256 + tid] = make_float4(hn[0], hn[1], hn[2], hn[3]);
        }

        // ---- Output partials: warp butterfly over columns ----
        #pragma unroll
        for (int p = 0; p < PAIRS; p++) {
            float ox = ov[p].x, oy = ov[p].y;
            #pragma unroll
            for (int off = 16; off; off >>= 1) {
                ox += __shfl_xor_sync(0xffffffffu, ox, off);
                oy += __shfl_xor_sync(0xffffffffu, oy, off);
            }
            if (lane == 0) part[hb][wid][p] = make_float2(ox, oy);
        }
        // no trailing sync: next step's top sync publishes hq[hb^1] and part[hb]
    }

    // Flush out[1023].
    __syncthreads();
    if (tid < MT) {
        int p = tid >> 1;
        float s = bo;
        #pragma unroll
        for (int w = 0; w < 8; w++) {
            float2 v = part[1][w][p];   // 1023 & 1
            s += (tid & 1) ? v.y : v.x;
        }
        out[(b0 + tid) * 1024 + 1023] = s;
    }
}

extern "C" void kernel_launch(void* const* d_in, const int* in_sizes, int n_in,
                              void* d_out, int out_size) {
    const float* x     = (const float*)d_in[0];
    const float* w_ih  = (const float*)d_in[1];
    const float* w_hh  = (const float*)d_in[2];
    const float* b_ih  = (const float*)d_in[3];
    const float* b_hh  = (const float*)d_in[4];
    const float* w_out = (const float*)d_in[5];
    const float* b_out = (const float*)d_in[6];
    float* out = (float*)d_out;

    k_transpose<<<768, 256>>>(w_hh);
    k_gru<<<1024, 256>>>(x, w_ih, b_ih, b_hh, w_out, b_out, out);
}